// round 4
// baseline (speedup 1.0000x reference)
#include <cuda_runtime.h>
#include <cuda_fp16.h>
#include <math.h>

#define TT     2048
#define INDIM  1024
#define HH     2048
#define G4     8192

#define NCTA   148
#define UPC    14              // hidden units per CTA (148*14 = 2072 >= 2048)
#define NTHR   1024
#define SMEM_W_BYTES (6 * HH * 8 * 2)                       // 48 rows fp16, grouped: 196608
#define SMEM_BYTES   (SMEM_W_BYTES + HH * 4 + 64 * 4 + 64)  // + hg(8KB) + gates(256B) + c

// ---------------- device scratch (static, allocation-free) ----------------
__device__ float  g_xg[(size_t)TT * G4];             // 64MB
__device__ float  g_gamma[(size_t)TT * HH];          // 16MB
__device__ float  g_hs[(size_t)TT * HH];             // 16MB
__device__ __align__(16) __half g_Wspill[(size_t)NCTA * HH * 8];  // 4.85MB rows 48..55 per CTA
__device__ float  g_attn[TT];
__device__ float  g_w[TT];
__device__ unsigned g_arrive;

// ======================= prep: gamma + counter reset =======================
__global__ __launch_bounds__(256) void prep_gamma(const float* __restrict__ time_,
                                                  const float* __restrict__ dw,
                                                  const float* __restrict__ db) {
    int t = blockIdx.x;
    float dtp = 0.f;
    if (t >= 2) dtp = time_[t - 1] - time_[t - 2];
    for (int j = threadIdx.x; j < HH; j += 256) {
        float v = 1.f;
        if (t >= 1) v = expf(-fmaxf(dtp * dw[j] + db[j], 0.f));
        g_gamma[(size_t)t * HH + j] = v;
    }
    if (blockIdx.x == 0 && threadIdx.x == 0) g_arrive = 0u;
}

// pack spill rows (local rows 48..55) as [cta][col][8 rows] fp16
__global__ __launch_bounds__(256) void prep_spill(const float* __restrict__ Whh) {
    int b = blockIdx.x;
    int u0 = b * UPC;
    for (int idx = threadIdx.x; idx < HH * 8; idx += 256) {
        int rg  = idx & 7;
        int col = idx >> 3;
        int r   = 48 + rg;
        int k    = r >> 2;
        int gate = r & 3;
        int u = u0 + k;
        float w = 0.f;
        if (u < HH) w = Whh[((size_t)gate * HH + u) * HH + col];
        g_Wspill[((size_t)b * HH + col) * 8 + rg] = __float2half(w);
    }
}

// ======================= xg GEMM: fp32 SIMT 128x128x8 =======================
__global__ __launch_bounds__(256) void gemm_xg(const float* __restrict__ x,
                                               const float* __restrict__ Wih,
                                               const float* __restrict__ bih,
                                               const float* __restrict__ bhh) {
    __shared__ float As[8][128];
    __shared__ float Bs[8][128];
    const int tid = threadIdx.x;
    const int tx = tid & 15, ty = tid >> 4;
    const int m0 = blockIdx.y * 128, n0 = blockIdx.x * 128;
    const int lr = tid >> 1;
    const int lk = (tid & 1) << 2;
    const float* aptr = x   + (size_t)(m0 + lr) * INDIM + lk;
    const float* bptr = Wih + (size_t)(n0 + lr) * INDIM + lk;

    float acc[8][8];
#pragma unroll
    for (int i = 0; i < 8; i++)
#pragma unroll
        for (int j = 0; j < 8; j++) acc[i][j] = 0.f;

    for (int k0 = 0; k0 < INDIM; k0 += 8) {
        float4 av = *(const float4*)(aptr + k0);
        float4 bv = *(const float4*)(bptr + k0);
        As[lk + 0][lr] = av.x; As[lk + 1][lr] = av.y; As[lk + 2][lr] = av.z; As[lk + 3][lr] = av.w;
        Bs[lk + 0][lr] = bv.x; Bs[lk + 1][lr] = bv.y; Bs[lk + 2][lr] = bv.z; Bs[lk + 3][lr] = bv.w;
        __syncthreads();
#pragma unroll
        for (int k = 0; k < 8; k++) {
            float a[8], bb[8];
            *(float4*)(a)      = *(const float4*)&As[k][ty * 8];
            *(float4*)(a + 4)  = *(const float4*)&As[k][ty * 8 + 4];
            *(float4*)(bb)     = *(const float4*)&Bs[k][tx * 8];
            *(float4*)(bb + 4) = *(const float4*)&Bs[k][tx * 8 + 4];
#pragma unroll
            for (int i = 0; i < 8; i++)
#pragma unroll
                for (int j = 0; j < 8; j++) acc[i][j] += a[i] * bb[j];
        }
        __syncthreads();
    }

    float bsum[8];
#pragma unroll
    for (int j = 0; j < 8; j++) {
        int n = n0 + tx * 8 + j;
        bsum[j] = bih[n] + bhh[n];
    }
#pragma unroll
    for (int i = 0; i < 8; i++) {
        int m = m0 + ty * 8 + i;
        float* o = g_xg + (size_t)m * G4 + n0 + tx * 8;
        float4 v0, v1;
        v0.x = acc[i][0] + bsum[0]; v0.y = acc[i][1] + bsum[1];
        v0.z = acc[i][2] + bsum[2]; v0.w = acc[i][3] + bsum[3];
        v1.x = acc[i][4] + bsum[4]; v1.y = acc[i][5] + bsum[5];
        v1.z = acc[i][6] + bsum[6]; v1.w = acc[i][7] + bsum[7];
        *(float4*)(o)     = v0;
        *(float4*)(o + 4) = v1;
    }
}

// ======================= persistent LSTM scan =======================
__global__ void __launch_bounds__(NTHR, 1) lstm_scan(const float* __restrict__ Whh,
                                                     const float* __restrict__ h0,
                                                     const float* __restrict__ c0in) {
    extern __shared__ __align__(16) char smem_raw[];
    __half* W_s     = (__half*)smem_raw;                       // 6 groups * 2048 cols * 8 rows
    float*  hg_s    = (float*)(smem_raw + SMEM_W_BYTES);       // 2048
    float*  gates_s = hg_s + HH;                               // 64
    float*  c_s     = gates_s + 64;                            // 14

    const int tid = threadIdx.x;
    const int b   = blockIdx.x;
    const int u0  = b * UPC;

    // ---- prologue: stage 48 rows into smem fp16, packed [grp][col][8] ----
    for (int r = 0; r < 48; r++) {
        int k = r >> 2, gate = r & 3;
        int u = u0 + k;
        int grp = r >> 3, rg = r & 7;
        __half* dst = W_s + (size_t)grp * (HH * 8) + rg;
        if (u < HH) {
            const float* src = Whh + ((size_t)gate * HH + u) * HH;
            for (int c = tid; c < HH; c += NTHR) dst[(size_t)c * 8] = __float2half(src[c]);
        } else {
            for (int c = tid; c < HH; c += NTHR) dst[(size_t)c * 8] = __float2half(0.f);
        }
    }
    if (tid < UPC) {
        int u = u0 + tid;
        c_s[tid] = (u < HH) ? c0in[u] : 0.f;
    }
    __syncthreads();

    const int warp = tid >> 5, lane = tid & 31;
    int grp, cbase;
    if (warp < 24) { grp = warp >> 2; cbase = (warp & 3) * 512; }
    else           { grp = 6;         cbase = (warp - 24) * 256; }
    const int rowbase = grp * 8;

    for (int t = 0; t < TT; t++) {
        // ---- stage h*gamma into smem; init gates with xg ----
        const float* hprev = (t == 0) ? h0 : (g_hs + (size_t)(t - 1) * HH);
        const float* grow  = g_gamma + (size_t)t * HH;
#pragma unroll
        for (int rr = 0; rr < 2; rr++) {
            int j = tid + rr * NTHR;
            float h = __ldcg(&hprev[j]);
            hg_s[j] = h * grow[j];
        }
        if (tid < 56) {
            int k = tid >> 2, gate = tid & 3;
            int u = u0 + k;
            float init = 0.f;
            if (u < HH) init = g_xg[(size_t)t * G4 + (size_t)gate * HH + u];
            gates_s[tid] = init;
        }
        __syncthreads();

        // ---- accumulate dot products ----
        float s[8];
#pragma unroll
        for (int j = 0; j < 8; j++) s[j] = 0.f;

        if (grp < 6) {
            const __half* wb = W_s + (size_t)grp * (HH * 8);
#pragma unroll 4
            for (int it = 0; it < 16; it++) {
                int col = cbase + it * 32 + lane;
                uint4 w = *(const uint4*)(wb + (size_t)col * 8);
                float hv = hg_s[col];
                float2 f0 = __half22float2(*(__half2*)&w.x);
                float2 f1 = __half22float2(*(__half2*)&w.y);
                float2 f2 = __half22float2(*(__half2*)&w.z);
                float2 f3 = __half22float2(*(__half2*)&w.w);
                s[0] += hv * f0.x; s[1] += hv * f0.y;
                s[2] += hv * f1.x; s[3] += hv * f1.y;
                s[4] += hv * f2.x; s[5] += hv * f2.y;
                s[6] += hv * f3.x; s[7] += hv * f3.y;
            }
        } else {
            const __half* wb = g_Wspill + (size_t)b * (HH * 8);
#pragma unroll 2
            for (int it = 0; it < 8; it++) {
                int col = cbase + it * 32 + lane;
                uint4 w = __ldg((const uint4*)(wb + (size_t)col * 8));
                float hv = hg_s[col];
                float2 f0 = __half22float2(*(__half2*)&w.x);
                float2 f1 = __half22float2(*(__half2*)&w.y);
                float2 f2 = __half22float2(*(__half2*)&w.z);
                float2 f3 = __half22float2(*(__half2*)&w.w);
                s[0] += hv * f0.x; s[1] += hv * f0.y;
                s[2] += hv * f1.x; s[3] += hv * f1.y;
                s[4] += hv * f2.x; s[5] += hv * f2.y;
                s[6] += hv * f3.x; s[7] += hv * f3.y;
            }
        }

#pragma unroll
        for (int j = 0; j < 8; j++) {
            float v = s[j];
            v += __shfl_xor_sync(0xffffffffu, v, 16);
            v += __shfl_xor_sync(0xffffffffu, v, 8);
            v += __shfl_xor_sync(0xffffffffu, v, 4);
            v += __shfl_xor_sync(0xffffffffu, v, 2);
            v += __shfl_xor_sync(0xffffffffu, v, 1);
            if (lane == j) atomicAdd(&gates_s[rowbase + j], v);
        }
        __syncthreads();

        // ---- gate math, write h ----
        if (tid < UPC) {
            int u = u0 + tid;
            if (u < HH) {
                float i_ = gates_s[tid * 4 + 0];
                float f_ = gates_s[tid * 4 + 1];
                float gg = gates_s[tid * 4 + 2];
                float o_ = gates_s[tid * 4 + 3];
                i_ = 1.f / (1.f + expf(-i_));
                f_ = 1.f / (1.f + expf(-f_));
                gg = tanhf(gg);
                o_ = 1.f / (1.f + expf(-o_));
                float c = f_ * c_s[tid] + i_ * gg;
                c_s[tid] = c;
                g_hs[(size_t)t * HH + u] = o_ * tanhf(c);
            }
        }
        __syncthreads();

        // ---- grid barrier, BOUNDED spin (hang -> diagnosable failure) ----
        if (t < TT - 1) {
            if (tid == 0) {
                __threadfence();
                atomicAdd(&g_arrive, 1u);
                unsigned target = (unsigned)NCTA * (unsigned)(t + 1);
                unsigned spins = 0u;
                while (*((volatile unsigned*)&g_arrive) < target) {
                    if (++spins > 100000u) break;   // ~17ms worst case; never hit when co-resident
                }
                __threadfence();
            }
            __syncthreads();
        }
    }
}

// ======================= attention pooling =======================
__global__ __launch_bounds__(256) void attn_scores() {
    __shared__ float red[8];
    const float* a = g_hs + (size_t)blockIdx.x * HH;
    const float* bf = g_hs + (size_t)(TT - 1) * HH;
    float s = 0.f;
    for (int j = threadIdx.x; j < HH; j += 256) s += a[j] * bf[j];
    for (int o = 16; o; o >>= 1) s += __shfl_xor_sync(0xffffffffu, s, o);
    if ((threadIdx.x & 31) == 0) red[threadIdx.x >> 5] = s;
    __syncthreads();
    if (threadIdx.x == 0) {
        float t = 0.f;
        for (int w = 0; w < 8; w++) t += red[w];
        g_attn[blockIdx.x] = t;
    }
}

__global__ __launch_bounds__(1024) void attn_softmax() {
    __shared__ float rmax[32], rsum[32];
    int tid = threadIdx.x;
    float v0 = g_attn[tid], v1 = g_attn[tid + 1024];
    float m = fmaxf(v0, v1);
    for (int o = 16; o; o >>= 1) m = fmaxf(m, __shfl_xor_sync(0xffffffffu, m, o));
    if ((tid & 31) == 0) rmax[tid >> 5] = m;
    __syncthreads();
    if (tid < 32) {
        float x = rmax[tid];
        for (int o = 16; o; o >>= 1) x = fmaxf(x, __shfl_xor_sync(0xffffffffu, x, o));
        rmax[tid] = x;
    }
    __syncthreads();
    float M = rmax[0];
    float e0 = expf(v0 - M), e1 = expf(v1 - M);
    float s = e0 + e1;
    for (int o = 16; o; o >>= 1) s += __shfl_xor_sync(0xffffffffu, s, o);
    if ((tid & 31) == 0) rsum[tid >> 5] = s;
    __syncthreads();
    if (tid < 32) {
        float x = rsum[tid];
        for (int o = 16; o; o >>= 1) x += __shfl_xor_sync(0xffffffffu, x, o);
        rsum[tid] = x;
    }
    __syncthreads();
    float inv = 1.f / rsum[0];
    g_w[tid] = e0 * inv;
    g_w[tid + 1024] = e1 * inv;
}

__global__ __launch_bounds__(256) void attn_context(float* __restrict__ out) {
    __shared__ float ws[TT];
    for (int i = threadIdx.x; i < TT; i += 256) ws[i] = g_w[i];
    __syncthreads();
    int j = blockIdx.x * 256 + threadIdx.x;
    float acc = 0.f;
#pragma unroll 8
    for (int t = 0; t < TT; t++) acc += ws[t] * g_hs[(size_t)t * HH + j];
    out[j] = acc;
}

// ======================= launch =======================
extern "C" void kernel_launch(void* const* d_in, const int* in_sizes, int n_in,
                              void* d_out, int out_size) {
    const float* x     = (const float*)d_in[0];
    const float* time_ = (const float*)d_in[1];
    const float* Wih   = (const float*)d_in[2];
    const float* Whh   = (const float*)d_in[3];
    const float* bih   = (const float*)d_in[4];
    const float* bhh   = (const float*)d_in[5];
    const float* dw    = (const float*)d_in[6];
    const float* db    = (const float*)d_in[7];
    const float* h0    = (const float*)d_in[8];
    const float* c0    = (const float*)d_in[9];
    float* out = (float*)d_out;

    cudaFuncSetAttribute(lstm_scan, cudaFuncAttributeMaxDynamicSharedMemorySize, SMEM_BYTES);

    prep_gamma<<<TT, 256>>>(time_, dw, db);
    prep_spill<<<NCTA, 256>>>(Whh);
    gemm_xg<<<dim3(G4 / 128, TT / 128), 256>>>(x, Wih, bih, bhh);
    lstm_scan<<<NCTA, NTHR, SMEM_BYTES>>>(Whh, h0, c0);
    attn_scores<<<TT, 256>>>();
    attn_softmax<<<1, 1024>>>();
    attn_context<<<HH / 256, 256>>>(out);
}

// round 7
// speedup vs baseline: 1.0950x; 1.0950x over previous
#include <cuda_runtime.h>
#include <cuda_fp16.h>
#include <math.h>

#define TT     2048
#define INDIM  1024
#define HH     2048
#define G4     8192

#define NCTA   148
#define UPC    14              // hidden units per CTA (148*14 = 2072 >= 2048)
#define NTHR   1024
#define SMEM_W_BYTES (6 * HH * 8 * 2)   // 48 rows fp16, 6 groups of 8: 196608

// smem layout offsets (bytes) after W
#define OFF_HG2   (SMEM_W_BYTES)                 // 2048 half2  = 8192
#define OFF_GAM   (OFF_HG2 + HH * 4)             // 2048 float  = 8192
#define OFF_XGP   (OFF_GAM + HH * 4)             // 64 float    = 256
#define OFF_PART  (OFF_XGP + 64 * 4)             // 32*8 float  = 1024
#define OFF_C     (OFF_PART + 256 * 4)           // 16 float
#define SMEM_BYTES (OFF_C + 16 * 4)

// ---------------- device scratch (static, allocation-free) ----------------
__device__ float  g_xg[(size_t)TT * G4];             // 64MB
__device__ float  g_gamma[(size_t)TT * HH];          // 16MB
__device__ float  g_hs[(size_t)TT * HH];             // 16MB
__device__ __align__(16) __half g_Wspill[(size_t)NCTA * HH * 8];  // rows 48..55 per CTA
__device__ float  g_attn[TT];
__device__ float  g_w[TT];
__device__ unsigned g_arrive;

// Reduce 8 fp32 values across a warp with 9 shfls (split-butterfly).
// Lane with (lane&3)==0 writes value j = 4*bit4 + 2*bit3 + bit2 to out[j].
__device__ __forceinline__ void warp_reduce8(float v[8], int lane, float* out) {
    const unsigned FULL = 0xffffffffu;
    bool b4 = (lane & 16) != 0;
    float k0 = b4 ? v[4] : v[0], g0 = b4 ? v[0] : v[4];
    float k1 = b4 ? v[5] : v[1], g1 = b4 ? v[1] : v[5];
    float k2 = b4 ? v[6] : v[2], g2 = b4 ? v[2] : v[6];
    float k3 = b4 ? v[7] : v[3], g3 = b4 ? v[3] : v[7];
    k0 += __shfl_xor_sync(FULL, g0, 16);
    k1 += __shfl_xor_sync(FULL, g1, 16);
    k2 += __shfl_xor_sync(FULL, g2, 16);
    k3 += __shfl_xor_sync(FULL, g3, 16);
    bool b3 = (lane & 8) != 0;
    float m0 = b3 ? k2 : k0, n0 = b3 ? k0 : k2;
    float m1 = b3 ? k3 : k1, n1 = b3 ? k1 : k3;
    m0 += __shfl_xor_sync(FULL, n0, 8);
    m1 += __shfl_xor_sync(FULL, n1, 8);
    bool b2 = (lane & 4) != 0;
    float p = b2 ? m1 : m0;
    float q = b2 ? m0 : m1;
    p += __shfl_xor_sync(FULL, q, 4);
    p += __shfl_xor_sync(FULL, p, 2);
    p += __shfl_xor_sync(FULL, p, 1);
    if ((lane & 3) == 0) {
        int j = ((lane >> 4) & 1) * 4 + ((lane >> 3) & 1) * 2 + ((lane >> 2) & 1);
        out[j] = p;
    }
}

// ======================= prep: gamma + counter reset =======================
__global__ __launch_bounds__(256) void prep_gamma(const float* __restrict__ time_,
                                                  const float* __restrict__ dw,
                                                  const float* __restrict__ db) {
    int t = blockIdx.x;
    float dtp = 0.f;
    if (t >= 2) dtp = time_[t - 1] - time_[t - 2];
    for (int j = threadIdx.x; j < HH; j += 256) {
        float v = 1.f;
        if (t >= 1) v = expf(-fmaxf(dtp * dw[j] + db[j], 0.f));
        g_gamma[(size_t)t * HH + j] = v;
    }
    if (blockIdx.x == 0 && threadIdx.x == 0) g_arrive = 0u;
}

// pack spill rows (local rows 48..55) as [cta][col][8 rows] fp16
__global__ __launch_bounds__(256) void prep_spill(const float* __restrict__ Whh) {
    int b = blockIdx.x;
    int u0 = b * UPC;
    for (int idx = threadIdx.x; idx < HH * 8; idx += 256) {
        int rg  = idx & 7;
        int col = idx >> 3;
        int r   = 48 + rg;
        int k    = r >> 2;
        int gate = r & 3;
        int u = u0 + k;
        float w = 0.f;
        if (u < HH) w = Whh[((size_t)gate * HH + u) * HH + col];
        g_Wspill[((size_t)b * HH + col) * 8 + rg] = __float2half(w);
    }
}

// ======================= xg GEMM: fp32 SIMT 128x128x8 =======================
__global__ __launch_bounds__(256) void gemm_xg(const float* __restrict__ x,
                                               const float* __restrict__ Wih,
                                               const float* __restrict__ bih,
                                               const float* __restrict__ bhh) {
    __shared__ float As[8][128];
    __shared__ float Bs[8][128];
    const int tid = threadIdx.x;
    const int tx = tid & 15, ty = tid >> 4;
    const int m0 = blockIdx.y * 128, n0 = blockIdx.x * 128;
    const int lr = tid >> 1;
    const int lk = (tid & 1) << 2;
    const float* aptr = x   + (size_t)(m0 + lr) * INDIM + lk;
    const float* bptr = Wih + (size_t)(n0 + lr) * INDIM + lk;

    float acc[8][8];
#pragma unroll
    for (int i = 0; i < 8; i++)
#pragma unroll
        for (int j = 0; j < 8; j++) acc[i][j] = 0.f;

    for (int k0 = 0; k0 < INDIM; k0 += 8) {
        float4 av = *(const float4*)(aptr + k0);
        float4 bv = *(const float4*)(bptr + k0);
        As[lk + 0][lr] = av.x; As[lk + 1][lr] = av.y; As[lk + 2][lr] = av.z; As[lk + 3][lr] = av.w;
        Bs[lk + 0][lr] = bv.x; Bs[lk + 1][lr] = bv.y; Bs[lk + 2][lr] = bv.z; Bs[lk + 3][lr] = bv.w;
        __syncthreads();
#pragma unroll
        for (int k = 0; k < 8; k++) {
            float a[8], bb[8];
            *(float4*)(a)      = *(const float4*)&As[k][ty * 8];
            *(float4*)(a + 4)  = *(const float4*)&As[k][ty * 8 + 4];
            *(float4*)(bb)     = *(const float4*)&Bs[k][tx * 8];
            *(float4*)(bb + 4) = *(const float4*)&Bs[k][tx * 8 + 4];
#pragma unroll
            for (int i = 0; i < 8; i++)
#pragma unroll
                for (int j = 0; j < 8; j++) acc[i][j] += a[i] * bb[j];
        }
        __syncthreads();
    }

    float bsum[8];
#pragma unroll
    for (int j = 0; j < 8; j++) {
        int n = n0 + tx * 8 + j;
        bsum[j] = bih[n] + bhh[n];
    }
#pragma unroll
    for (int i = 0; i < 8; i++) {
        int m = m0 + ty * 8 + i;
        float* o = g_xg + (size_t)m * G4 + n0 + tx * 8;
        float4 v0, v1;
        v0.x = acc[i][0] + bsum[0]; v0.y = acc[i][1] + bsum[1];
        v0.z = acc[i][2] + bsum[2]; v0.w = acc[i][3] + bsum[3];
        v1.x = acc[i][4] + bsum[4]; v1.y = acc[i][5] + bsum[5];
        v1.z = acc[i][6] + bsum[6]; v1.w = acc[i][7] + bsum[7];
        *(float4*)(o)     = v0;
        *(float4*)(o + 4) = v1;
    }
}

// ======================= persistent LSTM scan =======================
__global__ void __launch_bounds__(NTHR, 1) lstm_scan(const float* __restrict__ Whh,
                                                     const float* __restrict__ h0,
                                                     const float* __restrict__ c0in) {
    extern __shared__ __align__(16) char smem_raw[];
    __half*   W_s    = (__half*)smem_raw;
    __half2*  hg2_s  = (__half2*)(smem_raw + OFF_HG2);
    float*    gam_s  = (float*)(smem_raw + OFF_GAM);
    float*    xgp_s  = (float*)(smem_raw + OFF_XGP);
    float*    part_s = (float*)(smem_raw + OFF_PART);
    float*    c_s    = (float*)(smem_raw + OFF_C);

    const int tid = threadIdx.x;
    const int b   = blockIdx.x;
    const int u0  = b * UPC;

    // ---- prologue: stage 48 rows into smem fp16, packed [grp][col][8] ----
    for (int r = 0; r < 48; r++) {
        int k = r >> 2, gate = r & 3;
        int u = u0 + k;
        int grp = r >> 3, rg = r & 7;
        __half* dst = W_s + (size_t)grp * (HH * 8) + rg;
        if (u < HH) {
            const float* src = Whh + ((size_t)gate * HH + u) * HH;
            for (int c = tid; c < HH; c += NTHR) dst[(size_t)c * 8] = __float2half(src[c]);
        } else {
            for (int c = tid; c < HH; c += NTHR) dst[(size_t)c * 8] = __float2half(0.f);
        }
    }
    if (tid < UPC) {
        int u = u0 + tid;
        c_s[tid] = (u < HH) ? c0in[u] : 0.f;
    }
    // gamma(0) == 1; prefetch xg(0)
    gam_s[tid] = 1.f; gam_s[tid + 1024] = 1.f;
    if (tid < 56) {
        int k = tid >> 2, gate = tid & 3;
        int u = u0 + k;
        xgp_s[tid] = (u < HH) ? g_xg[(size_t)gate * HH + u] : 0.f;
    }
    __syncthreads();

    const int warp = tid >> 5, lane = tid & 31;
    int grp, cbase;
    if (warp < 24) { grp = warp >> 2; cbase = (warp & 3) * 512; }
    else           { grp = 6;         cbase = (warp - 24) * 256; }

    for (int t = 0; t < TT; t++) {
        // ---- A: stage h*gamma as broadcast half2 ----
        const float* hprev = (t == 0) ? h0 : (g_hs + (size_t)(t - 1) * HH);
        {
            float hv0 = __ldcg(&hprev[tid]);
            float hv1 = __ldcg(&hprev[tid + 1024]);
            hg2_s[tid]        = __float2half2_rn(hv0 * gam_s[tid]);
            hg2_s[tid + 1024] = __float2half2_rn(hv1 * gam_s[tid + 1024]);
        }
        __syncthreads();

        // ---- C: HFMA2 accumulate, dual banks (8-term fp16 chains) ----
        float s[8];
        {
            __half2 a0[4], a1[4];
            const __half2 z = __float2half2_rn(0.f);
#pragma unroll
            for (int p = 0; p < 4; p++) { a0[p] = z; a1[p] = z; }

            if (grp < 6) {
                const __half* wb = W_s + (size_t)grp * (HH * 8);
#pragma unroll
                for (int it = 0; it < 16; it++) {
                    int col = cbase + it * 32 + lane;
                    uint4 w = *(const uint4*)(wb + (size_t)col * 8);
                    __half2 h2 = hg2_s[col];
                    __half2* wp = (__half2*)&w;
                    if (it & 1) {
                        a1[0] = __hfma2(wp[0], h2, a1[0]);
                        a1[1] = __hfma2(wp[1], h2, a1[1]);
                        a1[2] = __hfma2(wp[2], h2, a1[2]);
                        a1[3] = __hfma2(wp[3], h2, a1[3]);
                    } else {
                        a0[0] = __hfma2(wp[0], h2, a0[0]);
                        a0[1] = __hfma2(wp[1], h2, a0[1]);
                        a0[2] = __hfma2(wp[2], h2, a0[2]);
                        a0[3] = __hfma2(wp[3], h2, a0[3]);
                    }
                }
            } else {
                const __half* wb = g_Wspill + (size_t)b * (HH * 8);
#pragma unroll
                for (int it = 0; it < 8; it++) {
                    int col = cbase + it * 32 + lane;
                    uint4 w = __ldg((const uint4*)(wb + (size_t)col * 8));
                    __half2 h2 = hg2_s[col];
                    __half2* wp = (__half2*)&w;
                    if (it & 1) {
                        a1[0] = __hfma2(wp[0], h2, a1[0]);
                        a1[1] = __hfma2(wp[1], h2, a1[1]);
                        a1[2] = __hfma2(wp[2], h2, a1[2]);
                        a1[3] = __hfma2(wp[3], h2, a1[3]);
                    } else {
                        a0[0] = __hfma2(wp[0], h2, a0[0]);
                        a0[1] = __hfma2(wp[1], h2, a0[1]);
                        a0[2] = __hfma2(wp[2], h2, a0[2]);
                        a0[3] = __hfma2(wp[3], h2, a0[3]);
                    }
                }
            }
#pragma unroll
            for (int p = 0; p < 4; p++) {
                float2 fa = __half22float2(a0[p]);
                float2 fb = __half22float2(a1[p]);
                s[2 * p]     = fa.x + fb.x;
                s[2 * p + 1] = fa.y + fb.y;
            }
        }

        // ---- D: warp reduce (9 shfls) + per-warp partial store ----
        warp_reduce8(s, lane, part_s + warp * 8);
        __syncthreads();

        // ---- F: gate math (14 threads) + prefetch next gamma/xg (others) ----
        if (tid < UPC) {
            int u = u0 + tid;
            if (u < HH) {
                float g4[4];
#pragma unroll
                for (int g = 0; g < 4; g++) {
                    int r = tid * 4 + g;
                    float tot = xgp_s[r];
                    if (r < 48) {
                        int gg = r >> 3, slot = r & 7;
#pragma unroll
                        for (int i = 0; i < 4; i++) tot += part_s[(4 * gg + i) * 8 + slot];
                    } else {
                        int slot = r - 48;
#pragma unroll
                        for (int i = 0; i < 8; i++) tot += part_s[(24 + i) * 8 + slot];
                    }
                    g4[g] = tot;
                }
                float i_ = 1.f / (1.f + __expf(-g4[0]));
                float f_ = 1.f / (1.f + __expf(-g4[1]));
                float gg = 2.f / (1.f + __expf(-2.f * g4[2])) - 1.f;
                float o_ = 1.f / (1.f + __expf(-g4[3]));
                float c = f_ * c_s[tid] + i_ * gg;
                c_s[tid] = c;
                float th = 2.f / (1.f + __expf(-2.f * c)) - 1.f;
                g_hs[(size_t)t * HH + u] = o_ * th;
            }
        } else if (tid >= 64 && t + 1 < TT) {
            // prefetch gamma(t+1)
            for (int j = tid - 64; j < HH; j += NTHR - 64)
                gam_s[j] = g_gamma[(size_t)(t + 1) * HH + j];
            // prefetch xg(t+1) slice
            if (tid < 120) {
                int r = tid - 64;
                int k = r >> 2, gate = r & 3;
                int u = u0 + k;
                xgp_s[r] = (u < HH) ? g_xg[(size_t)(t + 1) * G4 + (size_t)gate * HH + u] : 0.f;
            }
        }
        __syncthreads();

        // ---- grid barrier (bounded spin) ----
        if (t < TT - 1) {
            if (tid == 0) {
                __threadfence();
                atomicAdd(&g_arrive, 1u);
                unsigned target = (unsigned)NCTA * (unsigned)(t + 1);
                unsigned spins = 0u;
                while (*((volatile unsigned*)&g_arrive) < target) {
                    if (++spins > 200000u) break;
                }
                __threadfence();
            }
            __syncthreads();
        }
    }
}

// ======================= attention pooling =======================
__global__ __launch_bounds__(256) void attn_scores() {
    __shared__ float red[8];
    const float* a = g_hs + (size_t)blockIdx.x * HH;
    const float* bf = g_hs + (size_t)(TT - 1) * HH;
    float s = 0.f;
    for (int j = threadIdx.x; j < HH; j += 256) s += a[j] * bf[j];
    for (int o = 16; o; o >>= 1) s += __shfl_xor_sync(0xffffffffu, s, o);
    if ((threadIdx.x & 31) == 0) red[threadIdx.x >> 5] = s;
    __syncthreads();
    if (threadIdx.x == 0) {
        float t = 0.f;
        for (int w = 0; w < 8; w++) t += red[w];
        g_attn[blockIdx.x] = t;
    }
}

__global__ __launch_bounds__(1024) void attn_softmax() {
    __shared__ float rmax[32], rsum[32];
    int tid = threadIdx.x;
    float v0 = g_attn[tid], v1 = g_attn[tid + 1024];
    float m = fmaxf(v0, v1);
    for (int o = 16; o; o >>= 1) m = fmaxf(m, __shfl_xor_sync(0xffffffffu, m, o));
    if ((tid & 31) == 0) rmax[tid >> 5] = m;
    __syncthreads();
    if (tid < 32) {
        float x = rmax[tid];
        for (int o = 16; o; o >>= 1) x = fmaxf(x, __shfl_xor_sync(0xffffffffu, x, o));
        rmax[tid] = x;
    }
    __syncthreads();
    float M = rmax[0];
    float e0 = expf(v0 - M), e1 = expf(v1 - M);
    float s = e0 + e1;
    for (int o = 16; o; o >>= 1) s += __shfl_xor_sync(0xffffffffu, s, o);
    if ((tid & 31) == 0) rsum[tid >> 5] = s;
    __syncthreads();
    if (tid < 32) {
        float x = rsum[tid];
        for (int o = 16; o; o >>= 1) x += __shfl_xor_sync(0xffffffffu, x, o);
        rsum[tid] = x;
    }
    __syncthreads();
    float inv = 1.f / rsum[0];
    g_w[tid] = e0 * inv;
    g_w[tid + 1024] = e1 * inv;
}

__global__ __launch_bounds__(256) void attn_context(float* __restrict__ out) {
    __shared__ float ws[TT];
    for (int i = threadIdx.x; i < TT; i += 256) ws[i] = g_w[i];
    __syncthreads();
    int j = blockIdx.x * 256 + threadIdx.x;
    float acc = 0.f;
#pragma unroll 8
    for (int t = 0; t < TT; t++) acc += ws[t] * g_hs[(size_t)t * HH + j];
    out[j] = acc;
}

// ======================= launch =======================
extern "C" void kernel_launch(void* const* d_in, const int* in_sizes, int n_in,
                              void* d_out, int out_size) {
    const float* x     = (const float*)d_in[0];
    const float* time_ = (const float*)d_in[1];
    const float* Wih   = (const float*)d_in[2];
    const float* Whh   = (const float*)d_in[3];
    const float* bih   = (const float*)d_in[4];
    const float* bhh   = (const float*)d_in[5];
    const float* dw    = (const float*)d_in[6];
    const float* db    = (const float*)d_in[7];
    const float* h0    = (const float*)d_in[8];
    const float* c0    = (const float*)d_in[9];
    float* out = (float*)d_out;

    cudaFuncSetAttribute(lstm_scan, cudaFuncAttributeMaxDynamicSharedMemorySize, SMEM_BYTES);

    prep_gamma<<<TT, 256>>>(time_, dw, db);
    prep_spill<<<NCTA, 256>>>(Whh);
    gemm_xg<<<dim3(G4 / 128, TT / 128), 256>>>(x, Wih, bih, bhh);
    lstm_scan<<<NCTA, NTHR, SMEM_BYTES>>>(Whh, h0, c0);
    attn_scores<<<TT, 256>>>();
    attn_softmax<<<1, 1024>>>();
    attn_context<<<HH / 256, 256>>>(out);
}

// round 8
// speedup vs baseline: 1.5068x; 1.3761x over previous
#include <cuda_runtime.h>
#include <cuda_fp16.h>
#include <math.h>

#define TT     2048
#define INDIM  1024
#define HH     2048
#define G4     8192

#define NCTA   148
#define UPC    14              // hidden units per CTA (148*14 = 2072 >= 2048)
#define NTHR   1024

// ---- smem layout (bytes) ----
#define SMEM_W_BYTES (6 * HH * 8 * 2)            // 48 rows fp16, 6 groups of 8: 196608
#define OFF_HX    (SMEM_W_BYTES)                 // 2048 half2 = 8192
#define OFF_DTP   (OFF_HX + HH * 4)              // 2048 float = 8192
#define OFF_XGP   (OFF_DTP + HH * 4)             // 2*64 float = 512
#define OFF_PART  (OFF_XGP + 128 * 4)            // 32*8 float = 1024
#define SMEM_BYTES (OFF_PART + 256 * 4)          // 214528

// ---------------- device scratch (static, allocation-free) ----------------
__device__ float  g_xg[(size_t)TT * G4];             // 64MB
__device__ float  g_hs[(size_t)TT * HH];             // 16MB (raw h for attention)
__device__ __align__(16) __half g_Wspill[(size_t)NCTA * HH * 8];  // rows 48..55 per CTA
__device__ __align__(8) __half2 g_hx[2][HH];         // h*gamma exchange, parity buffered
__device__ float  g_attn[TT];
__device__ float  g_w[TT];
__device__ unsigned g_arrive;

__device__ __forceinline__ unsigned ld_acquire_u32(const unsigned* p) {
    unsigned v;
    asm volatile("ld.acquire.gpu.u32 %0, [%1];" : "=r"(v) : "l"(p) : "memory");
    return v;
}
__device__ __forceinline__ void red_release_add_u32(unsigned* p, unsigned v) {
    asm volatile("red.release.gpu.add.u32 [%0], %1;" :: "l"(p), "r"(v) : "memory");
}
__device__ __forceinline__ float sigmoid_f(float x) {
    return __fdividef(1.f, 1.f + __expf(-x));
}
__device__ __forceinline__ float tanh_f(float x) {
    return __fdividef(2.f, 1.f + __expf(-2.f * x)) - 1.f;
}

// Reduce 8 fp32 values across a warp with 9 shfls (split-butterfly).
// Lane with (lane&3)==0 writes value j = 4*bit4 + 2*bit3 + bit2 to out[j].
__device__ __forceinline__ void warp_reduce8(float v[8], int lane, float* out) {
    const unsigned FULL = 0xffffffffu;
    bool b4 = (lane & 16) != 0;
    float k0 = b4 ? v[4] : v[0], g0 = b4 ? v[0] : v[4];
    float k1 = b4 ? v[5] : v[1], g1 = b4 ? v[1] : v[5];
    float k2 = b4 ? v[6] : v[2], g2 = b4 ? v[2] : v[6];
    float k3 = b4 ? v[7] : v[3], g3 = b4 ? v[3] : v[7];
    k0 += __shfl_xor_sync(FULL, g0, 16);
    k1 += __shfl_xor_sync(FULL, g1, 16);
    k2 += __shfl_xor_sync(FULL, g2, 16);
    k3 += __shfl_xor_sync(FULL, g3, 16);
    bool b3 = (lane & 8) != 0;
    float m0 = b3 ? k2 : k0, n0 = b3 ? k0 : k2;
    float m1 = b3 ? k3 : k1, n1 = b3 ? k1 : k3;
    m0 += __shfl_xor_sync(FULL, n0, 8);
    m1 += __shfl_xor_sync(FULL, n1, 8);
    bool b2 = (lane & 4) != 0;
    float p = b2 ? m1 : m0;
    float q = b2 ? m0 : m1;
    p += __shfl_xor_sync(FULL, q, 4);
    p += __shfl_xor_sync(FULL, p, 2);
    p += __shfl_xor_sync(FULL, p, 1);
    if ((lane & 3) == 0) {
        int j = ((lane >> 4) & 1) * 4 + ((lane >> 3) & 1) * 2 + ((lane >> 2) & 1);
        out[j] = p;
    }
}

// ======== prep: spill pack + barrier reset + h0 broadcast into g_hx[0] ========
__global__ __launch_bounds__(256) void prep_spill(const float* __restrict__ Whh,
                                                  const float* __restrict__ h0) {
    int b = blockIdx.x;
    int u0 = b * UPC;
    for (int idx = threadIdx.x; idx < HH * 8; idx += 256) {
        int rg  = idx & 7;
        int col = idx >> 3;
        int r   = 48 + rg;
        int k    = r >> 2;
        int gate = r & 3;
        int u = u0 + k;
        float w = 0.f;
        if (u < HH) w = Whh[((size_t)gate * HH + u) * HH + col];
        g_Wspill[((size_t)b * HH + col) * 8 + rg] = __float2half(w);
    }
    if (b == 0) {
        if (threadIdx.x == 0) g_arrive = 0u;
        for (int j = threadIdx.x; j < HH; j += 256)
            g_hx[0][j] = __float2half2_rn(h0[j]);   // step 0: gamma = 1
    }
}

// ======================= xg GEMM: fp32 SIMT 128x128x8 =======================
__global__ __launch_bounds__(256) void gemm_xg(const float* __restrict__ x,
                                               const float* __restrict__ Wih,
                                               const float* __restrict__ bih,
                                               const float* __restrict__ bhh) {
    __shared__ float As[8][128];
    __shared__ float Bs[8][128];
    const int tid = threadIdx.x;
    const int tx = tid & 15, ty = tid >> 4;
    const int m0 = blockIdx.y * 128, n0 = blockIdx.x * 128;
    const int lr = tid >> 1;
    const int lk = (tid & 1) << 2;
    const float* aptr = x   + (size_t)(m0 + lr) * INDIM + lk;
    const float* bptr = Wih + (size_t)(n0 + lr) * INDIM + lk;

    float acc[8][8];
#pragma unroll
    for (int i = 0; i < 8; i++)
#pragma unroll
        for (int j = 0; j < 8; j++) acc[i][j] = 0.f;

    for (int k0 = 0; k0 < INDIM; k0 += 8) {
        float4 av = *(const float4*)(aptr + k0);
        float4 bv = *(const float4*)(bptr + k0);
        As[lk + 0][lr] = av.x; As[lk + 1][lr] = av.y; As[lk + 2][lr] = av.z; As[lk + 3][lr] = av.w;
        Bs[lk + 0][lr] = bv.x; Bs[lk + 1][lr] = bv.y; Bs[lk + 2][lr] = bv.z; Bs[lk + 3][lr] = bv.w;
        __syncthreads();
#pragma unroll
        for (int k = 0; k < 8; k++) {
            float a[8], bb[8];
            *(float4*)(a)      = *(const float4*)&As[k][ty * 8];
            *(float4*)(a + 4)  = *(const float4*)&As[k][ty * 8 + 4];
            *(float4*)(bb)     = *(const float4*)&Bs[k][tx * 8];
            *(float4*)(bb + 4) = *(const float4*)&Bs[k][tx * 8 + 4];
#pragma unroll
            for (int i = 0; i < 8; i++)
#pragma unroll
                for (int j = 0; j < 8; j++) acc[i][j] += a[i] * bb[j];
        }
        __syncthreads();
    }

    float bsum[8];
#pragma unroll
    for (int j = 0; j < 8; j++) {
        int n = n0 + tx * 8 + j;
        bsum[j] = bih[n] + bhh[n];
    }
#pragma unroll
    for (int i = 0; i < 8; i++) {
        int m = m0 + ty * 8 + i;
        float* o = g_xg + (size_t)m * G4 + n0 + tx * 8;
        float4 v0, v1;
        v0.x = acc[i][0] + bsum[0]; v0.y = acc[i][1] + bsum[1];
        v0.z = acc[i][2] + bsum[2]; v0.w = acc[i][3] + bsum[3];
        v1.x = acc[i][4] + bsum[4]; v1.y = acc[i][5] + bsum[5];
        v1.z = acc[i][6] + bsum[6]; v1.w = acc[i][7] + bsum[7];
        *(float4*)(o)     = v0;
        *(float4*)(o + 4) = v1;
    }
}

// ======================= persistent LSTM scan =======================
__global__ void __launch_bounds__(NTHR, 1) lstm_scan(const float* __restrict__ Whh,
                                                     const float* __restrict__ time_,
                                                     const float* __restrict__ dwp,
                                                     const float* __restrict__ dbp,
                                                     const float* __restrict__ c0in) {
    extern __shared__ __align__(16) char smem_raw[];
    __half*  W_s    = (__half*)smem_raw;
    __half2* hx_s   = (__half2*)(smem_raw + OFF_HX);
    float*   dtp_s  = (float*)(smem_raw + OFF_DTP);
    float*   xgp_s  = (float*)(smem_raw + OFF_XGP);    // [2][64]
    float*   part_s = (float*)(smem_raw + OFF_PART);   // [32][8]

    const int tid = threadIdx.x;
    const int b   = blockIdx.x;
    const int u0  = b * UPC;
    const int warp = tid >> 5, lane = tid & 31;

    // ---- prologue: stage 48 rows into smem fp16, packed [grp][col][8] ----
    for (int r = 0; r < 48; r++) {
        int k = r >> 2, gate = r & 3;
        int u = u0 + k;
        int grp = r >> 3, rg = r & 7;
        __half* dst = W_s + (size_t)grp * (HH * 8) + rg;
        if (u < HH) {
            const float* src = Whh + ((size_t)gate * HH + u) * HH;
            for (int c = tid; c < HH; c += NTHR) dst[(size_t)c * 8] = __float2half(src[c]);
        } else {
            for (int c = tid; c < HH; c += NTHR) dst[(size_t)c * 8] = __float2half(0.f);
        }
    }
    // dtp_s[t] = time[t-1] - time[t-2] for t>=2, else 0
    {
        int t0 = tid;
        dtp_s[t0] = (t0 >= 2) ? (time_[t0 - 1] - time_[t0 - 2]) : 0.f;
        int t1 = tid + 1024;
        dtp_s[t1] = time_[t1 - 1] - time_[t1 - 2];
    }
    // xg(0) into buffer 0
    if (tid < 56) {
        int k = tid >> 2, gate = tid & 3;
        int u = u0 + k;
        xgp_s[tid] = (u < HH) ? g_xg[(size_t)gate * HH + u] : 0.f;
    }

    // gate-lane registers: c, dw, db for owned unit
    float c_reg = 0.f, dw_reg = 0.f, db_reg = 0.f;
    int   my_u = HH;  // invalid by default
    if (warp < 2 && (lane & 3) == 0) {
        int r = warp * 32 + lane;          // row = 4*unit
        if (r < 56) {
            int unit = r >> 2;             // 0..13
            int u = u0 + unit;
            if (u < HH) {
                my_u  = u;
                c_reg = c0in[u];
                dw_reg = dwp[u];
                db_reg = dbp[u];
            }
        }
    }
    __syncthreads();

    int grp, cbase;
    if (warp < 24) { grp = warp >> 2; cbase = (warp & 3) * 512; }
    else           { grp = 6;         cbase = (warp - 24) * 256; }

    for (int t = 0; t < TT; t++) {
        // ---- A: stage h*gamma (already multiplied by producer) ----
        {
            const unsigned* src = (const unsigned*)g_hx[t & 1];
            unsigned v0 = __ldcg(&src[tid]);
            unsigned v1 = __ldcg(&src[tid + 1024]);
            ((unsigned*)hx_s)[tid]        = v0;
            ((unsigned*)hx_s)[tid + 1024] = v1;
        }
        __syncthreads();

        // ---- B: HFMA2 accumulate, dual banks ----
        float s[8];
        {
            __half2 a0[4], a1[4];
            const __half2 z = __float2half2_rn(0.f);
#pragma unroll
            for (int p = 0; p < 4; p++) { a0[p] = z; a1[p] = z; }

            if (grp < 6) {
                const __half* wb = W_s + (size_t)grp * (HH * 8);
#pragma unroll
                for (int it = 0; it < 16; it++) {
                    int col = cbase + it * 32 + lane;
                    uint4 w = *(const uint4*)(wb + (size_t)col * 8);
                    __half2 h2 = hx_s[col];
                    __half2* wp = (__half2*)&w;
                    if (it & 1) {
                        a1[0] = __hfma2(wp[0], h2, a1[0]);
                        a1[1] = __hfma2(wp[1], h2, a1[1]);
                        a1[2] = __hfma2(wp[2], h2, a1[2]);
                        a1[3] = __hfma2(wp[3], h2, a1[3]);
                    } else {
                        a0[0] = __hfma2(wp[0], h2, a0[0]);
                        a0[1] = __hfma2(wp[1], h2, a0[1]);
                        a0[2] = __hfma2(wp[2], h2, a0[2]);
                        a0[3] = __hfma2(wp[3], h2, a0[3]);
                    }
                }
            } else {
                const __half* wb = g_Wspill + (size_t)b * (HH * 8);
#pragma unroll
                for (int it = 0; it < 8; it++) {
                    int col = cbase + it * 32 + lane;
                    uint4 w = __ldg((const uint4*)(wb + (size_t)col * 8));
                    __half2 h2 = hx_s[col];
                    __half2* wp = (__half2*)&w;
                    if (it & 1) {
                        a1[0] = __hfma2(wp[0], h2, a1[0]);
                        a1[1] = __hfma2(wp[1], h2, a1[1]);
                        a1[2] = __hfma2(wp[2], h2, a1[2]);
                        a1[3] = __hfma2(wp[3], h2, a1[3]);
                    } else {
                        a0[0] = __hfma2(wp[0], h2, a0[0]);
                        a0[1] = __hfma2(wp[1], h2, a0[1]);
                        a0[2] = __hfma2(wp[2], h2, a0[2]);
                        a0[3] = __hfma2(wp[3], h2, a0[3]);
                    }
                }
            }
#pragma unroll
            for (int p = 0; p < 4; p++) {
                float2 fa = __half22float2(a0[p]);
                float2 fb = __half22float2(a1[p]);
                s[2 * p]     = fa.x + fb.x;
                s[2 * p + 1] = fa.y + fb.y;
            }
        }
        warp_reduce8(s, lane, part_s + warp * 8);
        __syncthreads();

        // ---- C: gate phase (warps 0-1), xg prefetch (warp 2) ----
        if (warp < 2) {
            int r  = warp * 32 + lane;
            int rr = (r < 56) ? r : 55;
            float tot = xgp_s[(t & 1) * 64 + rr];
            if (rr < 48) {
                int g = rr >> 3, slot = rr & 7;
                tot += part_s[(4 * g + 0) * 8 + slot] + part_s[(4 * g + 1) * 8 + slot]
                     + part_s[(4 * g + 2) * 8 + slot] + part_s[(4 * g + 3) * 8 + slot];
            } else {
                int slot = rr - 48;
#pragma unroll
                for (int i = 0; i < 8; i++) tot += part_s[(24 + i) * 8 + slot];
            }
            int role = rr & 3;
            float act = (role == 2) ? tanh_f(tot) : sigmoid_f(tot);
            int base = lane & ~3;
            float f_ = __shfl_sync(0xffffffffu, act, base + 1, 32);
            float gg = __shfl_sync(0xffffffffu, act, base + 2, 32);
            float o_ = __shfl_sync(0xffffffffu, act, base + 3, 32);
            if (my_u < HH) {
                c_reg = f_ * c_reg + act * gg;     // act = i gate on these lanes
                float th = tanh_f(c_reg);
                float h = o_ * th;
                g_hs[(size_t)t * HH + my_u] = h;
                if (t + 1 < TT) {
                    float z = fmaxf(dtp_s[t + 1] * dw_reg + db_reg, 0.f);
                    float gam = __expf(-z);
                    g_hx[(t + 1) & 1][my_u] = __float2half2_rn(h * gam);
                }
            }
            __syncwarp();
            if (lane == 0 && t + 1 < TT) red_release_add_u32(&g_arrive, 1u);
        } else if (warp == 2 && t + 1 < TT) {
            for (int q = lane; q < 56; q += 32) {
                int k = q >> 2, gate = q & 3;
                int u = u0 + k;
                xgp_s[((t + 1) & 1) * 64 + q] =
                    (u < HH) ? g_xg[(size_t)(t + 1) * G4 + (size_t)gate * HH + u] : 0.f;
            }
        }

        // ---- D: grid barrier wait ----
        if (t + 1 < TT) {
            if (tid == 0) {
                unsigned target = 2u * NCTA * (unsigned)(t + 1);
                unsigned spins = 0u;
                while (ld_acquire_u32(&g_arrive) < target) {
                    if (++spins > (1u << 22)) break;
                }
            }
            __syncthreads();
        }
    }
}

// ======================= attention pooling =======================
__global__ __launch_bounds__(256) void attn_scores() {
    __shared__ float red[8];
    const float* a = g_hs + (size_t)blockIdx.x * HH;
    const float* bf = g_hs + (size_t)(TT - 1) * HH;
    float s = 0.f;
    for (int j = threadIdx.x; j < HH; j += 256) s += a[j] * bf[j];
    for (int o = 16; o; o >>= 1) s += __shfl_xor_sync(0xffffffffu, s, o);
    if ((threadIdx.x & 31) == 0) red[threadIdx.x >> 5] = s;
    __syncthreads();
    if (threadIdx.x == 0) {
        float t = 0.f;
        for (int w = 0; w < 8; w++) t += red[w];
        g_attn[blockIdx.x] = t;
    }
}

__global__ __launch_bounds__(1024) void attn_softmax() {
    __shared__ float rmax[32], rsum[32];
    int tid = threadIdx.x;
    float v0 = g_attn[tid], v1 = g_attn[tid + 1024];
    float m = fmaxf(v0, v1);
    for (int o = 16; o; o >>= 1) m = fmaxf(m, __shfl_xor_sync(0xffffffffu, m, o));
    if ((tid & 31) == 0) rmax[tid >> 5] = m;
    __syncthreads();
    if (tid < 32) {
        float x = rmax[tid];
        for (int o = 16; o; o >>= 1) x = fmaxf(x, __shfl_xor_sync(0xffffffffu, x, o));
        rmax[tid] = x;
    }
    __syncthreads();
    float M = rmax[0];
    float e0 = expf(v0 - M), e1 = expf(v1 - M);
    float s = e0 + e1;
    for (int o = 16; o; o >>= 1) s += __shfl_xor_sync(0xffffffffu, s, o);
    if ((tid & 31) == 0) rsum[tid >> 5] = s;
    __syncthreads();
    if (tid < 32) {
        float x = rsum[tid];
        for (int o = 16; o; o >>= 1) x += __shfl_xor_sync(0xffffffffu, x, o);
        rsum[tid] = x;
    }
    __syncthreads();
    float inv = 1.f / rsum[0];
    g_w[tid] = e0 * inv;
    g_w[tid + 1024] = e1 * inv;
}

__global__ __launch_bounds__(256) void attn_context(float* __restrict__ out) {
    __shared__ float ws[TT];
    for (int i = threadIdx.x; i < TT; i += 256) ws[i] = g_w[i];
    __syncthreads();
    int j = blockIdx.x * 256 + threadIdx.x;
    float acc = 0.f;
#pragma unroll 8
    for (int t = 0; t < TT; t++) acc += ws[t] * g_hs[(size_t)t * HH + j];
    out[j] = acc;
}

// ======================= launch =======================
extern "C" void kernel_launch(void* const* d_in, const int* in_sizes, int n_in,
                              void* d_out, int out_size) {
    const float* x     = (const float*)d_in[0];
    const float* time_ = (const float*)d_in[1];
    const float* Wih   = (const float*)d_in[2];
    const float* Whh   = (const float*)d_in[3];
    const float* bih   = (const float*)d_in[4];
    const float* bhh   = (const float*)d_in[5];
    const float* dw    = (const float*)d_in[6];
    const float* db    = (const float*)d_in[7];
    const float* h0    = (const float*)d_in[8];
    const float* c0    = (const float*)d_in[9];
    float* out = (float*)d_out;

    cudaFuncSetAttribute(lstm_scan, cudaFuncAttributeMaxDynamicSharedMemorySize, SMEM_BYTES);

    prep_spill<<<NCTA, 256>>>(Whh, h0);
    gemm_xg<<<dim3(G4 / 128, TT / 128), 256>>>(x, Wih, bih, bhh);
    lstm_scan<<<NCTA, NTHR, SMEM_BYTES>>>(Whh, time_, dw, db, c0);
    attn_scores<<<TT, 256>>>();
    attn_softmax<<<1, 1024>>>();
    attn_context<<<HH / 256, 256>>>(out);
}